// round 15
// baseline (speedup 1.0000x reference)
#include <cuda_runtime.h>
#include <cuda_bf16.h>
#include <cstdint>

#define N_TOK 98
#define DIM   128
#define HEADS 4
#define NWIN  64
#define SCALE 0.17677669529663687f

#define MAX_B    2048
#define MAX_MTOT (MAX_B * N_TOK)

__device__ float g_qkv[(size_t)MAX_MTOT * 384];
__device__ float g_o[(size_t)MAX_MTOT * 128];
__device__ float g_comb[NWIN * HEADS * N_TOK * N_TOK];

// ======================= helpers =======================
static __device__ __forceinline__ uint32_t smem_u32(const void* p) {
    uint32_t a;
    asm("{ .reg .u64 t; cvta.to.shared.u64 t, %1; cvt.u32.u64 %0, t; }" : "=r"(a) : "l"(p));
    return a;
}
#define LDSM_X4(r0, r1, r2, r3, addr)                                          \
    asm volatile("ldmatrix.sync.aligned.m8n8.x4.shared.b16 {%0,%1,%2,%3}, [%4];" \
                 : "=r"(r0), "=r"(r1), "=r"(r2), "=r"(r3) : "r"(addr))
#define LDSM_X4_T(r0, r1, r2, r3, addr)                                        \
    asm volatile("ldmatrix.sync.aligned.m8n8.x4.trans.shared.b16 {%0,%1,%2,%3}, [%4];" \
                 : "=r"(r0), "=r"(r1), "=r"(r2), "=r"(r3) : "r"(addr))
#define MMA_BF16(c, a, b0, b1)                                                 \
    asm volatile("mma.sync.aligned.m16n8k16.row.col.f32.bf16.bf16.f32 "        \
                 "{%0,%1,%2,%3}, {%4,%5,%6,%7}, {%8,%9}, {%0,%1,%2,%3};"       \
                 : "+f"((c)[0]), "+f"((c)[1]), "+f"((c)[2]), "+f"((c)[3])      \
                 : "r"((a)[0]), "r"((a)[1]), "r"((a)[2]), "r"((a)[3]),         \
                   "r"(b0), "r"(b1))

static __device__ __forceinline__ void bf16split(float a, __nv_bfloat16& h, __nv_bfloat16& l) {
    h = __float2bfloat16_rn(a);
    l = __float2bfloat16_rn(a - __bfloat162float(h));
}
static __device__ __forceinline__ uint32_t pack_split(float a, float b, uint32_t& lo) {
    __nv_bfloat16 ah, al, bh, bl;
    bf16split(a, ah, al); bf16split(b, bh, bl);
    uint16_t ahu = *(uint16_t*)&ah, alu = *(uint16_t*)&al;
    uint16_t bhu = *(uint16_t*)&bh, blu = *(uint16_t*)&bl;
    lo = ((uint32_t)blu << 16) | alu;
    return ((uint32_t)bhu << 16) | ahu;
}

extern __shared__ char smraw[];

// ======================= bf16x3 GEMM: Out[M,N] = A[M,128] @ W[N,128]^T + bias ====================
#define G_AHI 0
#define G_ALO 34816
#define G_WHI 69632
#define G_WLO 88064
#define G_SMEM_BYTES 106496

__global__ __launch_bounds__(256, 2)
void gemm_bf16x3(const float* __restrict__ A,
                 const float* __restrict__ W,
                 const float* __restrict__ bias,
                 float* __restrict__ Out,
                 int Nout, int Mtot, int Ntiles)
{
    __nv_bfloat16* sb = (__nv_bfloat16*)smraw;
    const uint32_t sbase = smem_u32(sb);
    const int tid  = threadIdx.x;
    const int lane = tid & 31;
    const int warp = tid >> 5;
    const int wm   = warp & 3;
    const int wn   = warp >> 2;
    const long row0 = (long)blockIdx.x * 128;

    // ---- stage A [128 x 128] -> hi/lo bf16, stride 136 (once per block) ----
#pragma unroll 4
    for (int jj = 0; jj < 16; jj++) {
        int lin = tid + jj * 256;
        int r = lin >> 5, c = (lin & 31) * 4;
        float4 v = make_float4(0.f, 0.f, 0.f, 0.f);
        if (row0 + r < Mtot) v = *(const float4*)&A[(row0 + r) * 128 + c];
        __nv_bfloat16 h0, l0, h1, l1, h2, l2, h3, l3;
        bf16split(v.x, h0, l0); bf16split(v.y, h1, l1);
        bf16split(v.z, h2, l2); bf16split(v.w, h3, l3);
        int o = r * 136 + c;
        sb[(G_AHI>>1) + o] = h0; sb[(G_AHI>>1) + o + 1] = h1; sb[(G_AHI>>1) + o + 2] = h2; sb[(G_AHI>>1) + o + 3] = h3;
        sb[(G_ALO>>1) + o] = l0; sb[(G_ALO>>1) + o + 1] = l1; sb[(G_ALO>>1) + o + 2] = l2; sb[(G_ALO>>1) + o + 3] = l3;
    }

    const int a_row = wm * 32 + (lane & 15);
    const int a_cs  = (lane >> 4) * 8;
    const int b_i   = lane >> 3;
    const int b_rp  = (b_i >> 1) * 8 + (lane & 7);
    const int b_cs  = (b_i & 1) * 8;
    const int er = lane >> 2;
    const int ec = (lane & 3) * 2;

#pragma unroll 1
    for (int nc = 0; nc < Ntiles; nc++) {
        const int col0 = nc * 128;

        float acc[2][8][4];
#pragma unroll
        for (int mt = 0; mt < 2; mt++)
#pragma unroll
            for (int nt = 0; nt < 8; nt++)
#pragma unroll
                for (int i = 0; i < 4; i++) acc[mt][nt][i] = 0.f;

#pragma unroll 1
        for (int kc = 0; kc < 2; kc++) {
            __syncthreads();
#pragma unroll
            for (int jj = 0; jj < 8; jj++) {
                int lin = tid + jj * 256;
                int r = lin >> 4, c = (lin & 15) * 4;
                float4 v = *(const float4*)&W[(size_t)(col0 + r) * 128 + kc * 64 + c];
                __nv_bfloat16 h0, l0, h1, l1, h2, l2, h3, l3;
                bf16split(v.x, h0, l0); bf16split(v.y, h1, l1);
                bf16split(v.z, h2, l2); bf16split(v.w, h3, l3);
                int o = r * 72 + c;
                sb[(G_WHI>>1) + o] = h0; sb[(G_WHI>>1) + o + 1] = h1; sb[(G_WHI>>1) + o + 2] = h2; sb[(G_WHI>>1) + o + 3] = h3;
                sb[(G_WLO>>1) + o] = l0; sb[(G_WLO>>1) + o + 1] = l1; sb[(G_WLO>>1) + o + 2] = l2; sb[(G_WLO>>1) + o + 3] = l3;
            }
            __syncthreads();

#pragma unroll
            for (int ks = 0; ks < 4; ks++) {
                uint32_t ah[2][4], al[2][4];
#pragma unroll
                for (int mt = 0; mt < 2; mt++) {
                    uint32_t off = (uint32_t)((a_row + mt * 16) * 136 + kc * 64 + ks * 16 + a_cs) * 2;
                    LDSM_X4(ah[mt][0], ah[mt][1], ah[mt][2], ah[mt][3], sbase + G_AHI + off);
                    LDSM_X4(al[mt][0], al[mt][1], al[mt][2], al[mt][3], sbase + G_ALO + off);
                }
#pragma unroll
                for (int np = 0; np < 4; np++) {
                    uint32_t off = (uint32_t)((wn * 64 + np * 16 + b_rp) * 72 + ks * 16 + b_cs) * 2;
                    uint32_t h0, h1, h2, h3, l0, l1, l2, l3;
                    LDSM_X4(h0, h1, h2, h3, sbase + G_WHI + off);
                    LDSM_X4(l0, l1, l2, l3, sbase + G_WLO + off);
#pragma unroll
                    for (int mt = 0; mt < 2; mt++) {
                        MMA_BF16(acc[mt][np * 2],     ah[mt], h0, h1);
                        MMA_BF16(acc[mt][np * 2],     al[mt], h0, h1);
                        MMA_BF16(acc[mt][np * 2],     ah[mt], l0, l1);
                        MMA_BF16(acc[mt][np * 2 + 1], ah[mt], h2, h3);
                        MMA_BF16(acc[mt][np * 2 + 1], al[mt], h2, h3);
                        MMA_BF16(acc[mt][np * 2 + 1], ah[mt], l2, l3);
                    }
                }
            }
        }

#pragma unroll
        for (int mt = 0; mt < 2; mt++) {
            long r = row0 + wm * 32 + mt * 16 + er;
#pragma unroll
            for (int nt = 0; nt < 8; nt++) {
                int c = col0 + wn * 64 + nt * 8 + ec;
                float b0 = bias[c], b1 = bias[c + 1];
                if (r < Mtot)
                    *(float2*)&Out[r * Nout + c] =
                        make_float2(acc[mt][nt][0] + b0, acc[mt][nt][1] + b1);
                if (r + 8 < Mtot)
                    *(float2*)&Out[(r + 8) * Nout + c] =
                        make_float2(acc[mt][nt][2] + b0, acc[mt][nt][3] + b1);
            }
        }
    }
}

// ======================= comb = bias_table[rel_idx] + mask =======================
__global__ void comb_kernel(const float* __restrict__ mask,
                            const float* __restrict__ bias_table,
                            const int*   __restrict__ rel_idx)
{
    int idx = blockIdx.x * blockDim.x + threadIdx.x;
    const int total = NWIN * HEADS * N_TOK * N_TOK;
    if (idx >= total) return;
    int w   = idx / (HEADS * N_TOK * N_TOK);
    int rem = idx - w * (HEADS * N_TOK * N_TOK);
    int h   = rem / (N_TOK * N_TOK);
    int nm  = rem - h * (N_TOK * N_TOK);
    g_comb[idx] = bias_table[rel_idx[nm] * HEADS + h] + mask[w * (N_TOK * N_TOK) + nm];
}

// ======================= attention: staged-V-overlap register flash =======================
#define TQH 0
#define TQL 30464
#define TKH 60928
#define TKL 91392
#define TVH 121856
#define TVL 152320
#define ATTN_SMEM 182784
#define ATHREADS 448

// QK^T for item (h, mt) -> acc
static __device__ __forceinline__ void qkt_item(float (&acc)[14][4], uint32_t sbase,
                                                int h, int mt, int lane)
{
    const int a_rp = lane & 15;
    const int a_cs = (lane >> 4) * 8;
    const int b_i  = lane >> 3;
    const int b_rp = (b_i >> 1) * 8 + (lane & 7);
    const int b_cs = (b_i & 1) * 8;
#pragma unroll
    for (int nt = 0; nt < 14; nt++)
#pragma unroll
        for (int i = 0; i < 4; i++) acc[nt][i] = 0.f;
#pragma unroll
    for (int ks = 0; ks < 2; ks++) {
        const int kb = h * 32 + ks * 16;
        uint32_t ah[4], al[4];
        uint32_t aoff = (uint32_t)((mt * 16 + a_rp) * 136 + kb + a_cs) * 2;
        LDSM_X4(ah[0], ah[1], ah[2], ah[3], sbase + TQH + aoff);
        LDSM_X4(al[0], al[1], al[2], al[3], sbase + TQL + aoff);
#pragma unroll
        for (int np = 0; np < 7; np++) {
            uint32_t boff = (uint32_t)((np * 16 + b_rp) * 136 + kb + b_cs) * 2;
            uint32_t h0, h1, h2, h3, l0, l1, l2, l3;
            LDSM_X4(h0, h1, h2, h3, sbase + TKH + boff);
            LDSM_X4(l0, l1, l2, l3, sbase + TKL + boff);
            MMA_BF16(acc[np * 2],     ah, h0, h1);
            MMA_BF16(acc[np * 2],     al, h0, h1);
            MMA_BF16(acc[np * 2],     ah, l0, l1);
            MMA_BF16(acc[np * 2 + 1], ah, h2, h3);
            MMA_BF16(acc[np * 2 + 1], al, h2, h3);
            MMA_BF16(acc[np * 2 + 1], ah, l2, l3);
        }
    }
}

static __device__ __forceinline__ void softmax_item(float (&acc)[14][4],
                                                    const float* __restrict__ combh,
                                                    int mt, int lane)
{
    const int er = lane >> 2;
    const int ec = (lane & 3) * 2;
#pragma unroll
    for (int rr = 0; rr < 2; rr++) {
        int n = mt * 16 + er + rr * 8;
        bool rowok = (n < N_TOK);
        int  nc = rowok ? n : 0;
        float mx = -1e30f;
#pragma unroll
        for (int nt = 0; nt < 14; nt++) {
            int m = nt * 8 + ec;
            float v0 = -1e30f, v1 = -1e30f;
            if (m < N_TOK) {
                float2 cb = *(const float2*)&combh[nc * N_TOK + m];
                v0 = acc[nt][rr * 2]     + cb.x;
                v1 = acc[nt][rr * 2 + 1] + cb.y;
            }
            acc[nt][rr * 2] = v0; acc[nt][rr * 2 + 1] = v1;
            mx = fmaxf(mx, fmaxf(v0, v1));
        }
        mx = fmaxf(mx, __shfl_xor_sync(0xffffffffu, mx, 1));
        mx = fmaxf(mx, __shfl_xor_sync(0xffffffffu, mx, 2));
        float sum = 0.f;
#pragma unroll
        for (int nt = 0; nt < 14; nt++) {
            float e0 = __expf(acc[nt][rr * 2]     - mx);
            float e1 = __expf(acc[nt][rr * 2 + 1] - mx);
            acc[nt][rr * 2] = e0; acc[nt][rr * 2 + 1] = e1;
            sum += e0 + e1;
        }
        sum += __shfl_xor_sync(0xffffffffu, sum, 1);
        sum += __shfl_xor_sync(0xffffffffu, sum, 2);
        float inv = rowok ? __fdividef(1.f, sum) : 0.f;
#pragma unroll
        for (int nt = 0; nt < 14; nt++) {
            acc[nt][rr * 2] *= inv; acc[nt][rr * 2 + 1] *= inv;
        }
    }
}

static __device__ __forceinline__ void pv_item(float (&acc)[14][4], uint32_t sbase,
                                               int h, int mt, int lane, int b)
{
    const int b_i  = lane >> 3;
    const int t_rp = (b_i & 1) * 8 + (lane & 7);
    const int t_cs = (b_i >> 1) * 8;
    const int er   = lane >> 2;
    const int ec   = (lane & 3) * 2;

    float oacc[4][4];
#pragma unroll
    for (int nt = 0; nt < 4; nt++)
#pragma unroll
        for (int i = 0; i < 4; i++) oacc[nt][i] = 0.f;

#pragma unroll
    for (int t = 0; t < 7; t++) {
        uint32_t ph[4], pl[4];
        ph[0] = pack_split(acc[2*t][0],   acc[2*t][1],   pl[0]);
        ph[1] = pack_split(acc[2*t][2],   acc[2*t][3],   pl[1]);
        ph[2] = pack_split(acc[2*t+1][0], acc[2*t+1][1], pl[2]);
        ph[3] = pack_split(acc[2*t+1][2], acc[2*t+1][3], pl[3]);
#pragma unroll
        for (int np = 0; np < 2; np++) {
            uint32_t boff = (uint32_t)((t * 16 + t_rp) * 136 + h * 32 + np * 16 + t_cs) * 2;
            uint32_t h0, h1, h2, h3, l0, l1, l2, l3;
            LDSM_X4_T(h0, h1, h2, h3, sbase + TVH + boff);
            LDSM_X4_T(l0, l1, l2, l3, sbase + TVL + boff);
            MMA_BF16(oacc[np * 2],     ph, h0, h1);
            MMA_BF16(oacc[np * 2],     pl, h0, h1);
            MMA_BF16(oacc[np * 2],     ph, l0, l1);
            MMA_BF16(oacc[np * 2 + 1], ph, h2, h3);
            MMA_BF16(oacc[np * 2 + 1], pl, h2, h3);
            MMA_BF16(oacc[np * 2 + 1], ph, l2, l3);
        }
    }
    const int n0 = mt * 16 + er;
#pragma unroll
    for (int nt = 0; nt < 4; nt++) {
        int ch = h * 32 + nt * 8 + ec;
        if (n0 < N_TOK)
            *(float2*)&g_o[((size_t)b * N_TOK + n0) * 128 + ch] =
                make_float2(oacc[nt][0], oacc[nt][1]);
        if (n0 + 8 < N_TOK)
            *(float2*)&g_o[((size_t)b * N_TOK + n0 + 8) * 128 + ch] =
                make_float2(oacc[nt][2], oacc[nt][3]);
    }
}

__global__ __launch_bounds__(ATHREADS, 1)
void attn_kernel()
{
    char* sb = smraw;
    const uint32_t sbase = smem_u32(sb);
    const int b    = blockIdx.x;
    const int tid  = threadIdx.x;
    const int lane = tid & 31;
    const int warp = tid >> 5;
    const int win  = b & (NWIN - 1);

    const float* qk = g_qkv + (size_t)b * N_TOK * 384;

    // zero V pad rows 98..111 (hi/lo)
    for (int i = tid; i < 14 * 68; i += ATHREADS) {
        int r = 98 + i / 68, c4 = (i % 68) * 2;
        *(uint32_t*)(sb + TVH + (r * 136 + c4) * 2) = 0u;
        *(uint32_t*)(sb + TVL + (r * 136 + c4) * 2) = 0u;
    }

    // ---- stage Q (scaled) and K only ----
    for (int i = tid; i < N_TOK * 32; i += ATHREADS) {
        int m = i >> 5, c = (i & 31) * 4;
        const float* rp = qk + m * 384 + c;
        float4 q = *(const float4*)rp;
        float4 k = *(const float4*)(rp + 128);
        q.x *= SCALE; q.y *= SCALE; q.z *= SCALE; q.w *= SCALE;
        __nv_bfloat16 hh[4], ll[4];
        bf16split(q.x, hh[0], ll[0]); bf16split(q.y, hh[1], ll[1]);
        bf16split(q.z, hh[2], ll[2]); bf16split(q.w, hh[3], ll[3]);
        *(uint2*)(sb + TQH + (m * 136 + c) * 2) = *(uint2*)hh;
        *(uint2*)(sb + TQL + (m * 136 + c) * 2) = *(uint2*)ll;
        bf16split(k.x, hh[0], ll[0]); bf16split(k.y, hh[1], ll[1]);
        bf16split(k.z, hh[2], ll[2]); bf16split(k.w, hh[3], ll[3]);
        *(uint2*)(sb + TKH + (m * 136 + c) * 2) = *(uint2*)hh;
        *(uint2*)(sb + TKL + (m * 136 + c) * 2) = *(uint2*)ll;
    }
    __syncthreads();

    const int h0  = warp / 7,        mt0 = warp - h0 * 7;
    const int it1 = warp + 14;
    const int h1  = it1 / 7,         mt1 = it1 - h1 * 7;
    const float* combw = g_comb + (size_t)(win * HEADS) * N_TOK * N_TOK;

    float acc[14][4];

    // ---- pass 0: QK^T(item0), then stage this warp's V rows, softmax, sync, PV ----
    qkt_item(acc, sbase, h0, mt0, lane);

    {   // stage V rows 7*warp .. 7*warp+6 (each lane: one float4 per row)
        const int c = lane & 31;   // 0..31 float4 index
#pragma unroll
        for (int rr = 0; rr < 7; rr++) {
            int m = warp * 7 + rr;
            float4 v = *(const float4*)(qk + m * 384 + 256 + c * 4);
            __nv_bfloat16 hh[4], ll[4];
            bf16split(v.x, hh[0], ll[0]); bf16split(v.y, hh[1], ll[1]);
            bf16split(v.z, hh[2], ll[2]); bf16split(v.w, hh[3], ll[3]);
            *(uint2*)(sb + TVH + (m * 136 + c * 4) * 2) = *(uint2*)hh;
            *(uint2*)(sb + TVL + (m * 136 + c * 4) * 2) = *(uint2*)ll;
        }
    }

    softmax_item(acc, combw + (size_t)h0 * N_TOK * N_TOK, mt0, lane);
    __syncthreads();                 // V now visible to all warps
    pv_item(acc, sbase, h0, mt0, lane, b);

    // ---- pass 1: fully sync-free ----
    qkt_item(acc, sbase, h1, mt1, lane);
    softmax_item(acc, combw + (size_t)h1 * N_TOK * N_TOK, mt1, lane);
    pv_item(acc, sbase, h1, mt1, lane, b);
}

// ======================= launch =======================
extern "C" void kernel_launch(void* const* d_in, const int* in_sizes, int n_in,
                              void* d_out, int out_size)
{
    const float* x          = (const float*)d_in[0];
    const float* mask       = (const float*)d_in[1];
    const float* qkv_w      = (const float*)d_in[2];
    const float* qkv_b      = (const float*)d_in[3];
    const float* proj_w     = (const float*)d_in[4];
    const float* proj_b     = (const float*)d_in[5];
    const float* bias_table = (const float*)d_in[6];
    const int*   rel_idx    = (const int*)d_in[7];
    float*       out        = (float*)d_out;

    const int B    = in_sizes[0] / (N_TOK * DIM);
    const int Mtot = B * N_TOK;
    const int mtiles = (Mtot + 127) / 128;

    float *qkv_ptr, *o_ptr;
    cudaGetSymbolAddress((void**)&qkv_ptr, g_qkv);
    cudaGetSymbolAddress((void**)&o_ptr, g_o);

    cudaFuncSetAttribute(gemm_bf16x3,
                         cudaFuncAttributeMaxDynamicSharedMemorySize, G_SMEM_BYTES);
    cudaFuncSetAttribute(attn_kernel,
                         cudaFuncAttributeMaxDynamicSharedMemorySize, ATTN_SMEM);

    {
        const int total = NWIN * HEADS * N_TOK * N_TOK;
        comb_kernel<<<(total + 255) / 256, 256>>>(mask, bias_table, rel_idx);
    }
    gemm_bf16x3<<<mtiles, 256, G_SMEM_BYTES>>>(x, qkv_w, qkv_b, qkv_ptr, 384, Mtot, 3);
    attn_kernel<<<B, ATHREADS, ATTN_SMEM>>>();
    gemm_bf16x3<<<mtiles, 256, G_SMEM_BYTES>>>(o_ptr, proj_w, proj_b, out, 128, Mtot, 1);
}

// round 16
// speedup vs baseline: 1.0219x; 1.0219x over previous
#include <cuda_runtime.h>
#include <cuda_bf16.h>
#include <cstdint>

#define N_TOK 98
#define DIM   128
#define HEADS 4
#define NWIN  64
#define SCALE 0.17677669529663687f

#define MAX_B    2048
#define MAX_MTOT (MAX_B * N_TOK)

__device__ float g_qkv[(size_t)MAX_MTOT * 384];
__device__ float g_o[(size_t)MAX_MTOT * 128];
__device__ float g_comb[NWIN * HEADS * N_TOK * N_TOK];

// ======================= helpers =======================
static __device__ __forceinline__ uint32_t smem_u32(const void* p) {
    uint32_t a;
    asm("{ .reg .u64 t; cvta.to.shared.u64 t, %1; cvt.u32.u64 %0, t; }" : "=r"(a) : "l"(p));
    return a;
}
#define LDSM_X4(r0, r1, r2, r3, addr)                                          \
    asm volatile("ldmatrix.sync.aligned.m8n8.x4.shared.b16 {%0,%1,%2,%3}, [%4];" \
                 : "=r"(r0), "=r"(r1), "=r"(r2), "=r"(r3) : "r"(addr))
#define LDSM_X4_T(r0, r1, r2, r3, addr)                                        \
    asm volatile("ldmatrix.sync.aligned.m8n8.x4.trans.shared.b16 {%0,%1,%2,%3}, [%4];" \
                 : "=r"(r0), "=r"(r1), "=r"(r2), "=r"(r3) : "r"(addr))
#define MMA_BF16(c, a, b0, b1)                                                 \
    asm volatile("mma.sync.aligned.m16n8k16.row.col.f32.bf16.bf16.f32 "        \
                 "{%0,%1,%2,%3}, {%4,%5,%6,%7}, {%8,%9}, {%0,%1,%2,%3};"       \
                 : "+f"((c)[0]), "+f"((c)[1]), "+f"((c)[2]), "+f"((c)[3])      \
                 : "r"((a)[0]), "r"((a)[1]), "r"((a)[2]), "r"((a)[3]),         \
                   "r"(b0), "r"(b1))

static __device__ __forceinline__ void bf16split(float a, __nv_bfloat16& h, __nv_bfloat16& l) {
    h = __float2bfloat16_rn(a);
    l = __float2bfloat16_rn(a - __bfloat162float(h));
}
static __device__ __forceinline__ uint32_t pack_split(float a, float b, uint32_t& lo) {
    __nv_bfloat16 ah, al, bh, bl;
    bf16split(a, ah, al); bf16split(b, bh, bl);
    uint16_t ahu = *(uint16_t*)&ah, alu = *(uint16_t*)&al;
    uint16_t bhu = *(uint16_t*)&bh, blu = *(uint16_t*)&bl;
    lo = ((uint32_t)blu << 16) | alu;
    return ((uint32_t)bhu << 16) | ahu;
}

extern __shared__ char smraw[];

// ======================= bf16x3 GEMM: Out[M,N] = A[M,128] @ W[N,128]^T + bias ====================
// A staged once per block; nc loop over 128-col W slabs; wave-ordered mma (independent accs).
#define G_AHI 0
#define G_ALO 34816
#define G_WHI 69632
#define G_WLO 88064
#define G_SMEM_BYTES 106496

__global__ __launch_bounds__(256, 2)
void gemm_bf16x3(const float* __restrict__ A,
                 const float* __restrict__ W,
                 const float* __restrict__ bias,
                 float* __restrict__ Out,
                 int Nout, int Mtot, int Ntiles)
{
    __nv_bfloat16* sb = (__nv_bfloat16*)smraw;
    const uint32_t sbase = smem_u32(sb);
    const int tid  = threadIdx.x;
    const int lane = tid & 31;
    const int warp = tid >> 5;
    const int wm   = warp & 3;
    const int wn   = warp >> 2;
    const long row0 = (long)blockIdx.x * 128;

    // ---- stage A [128 x 128] -> hi/lo bf16, stride 136 (once per block) ----
#pragma unroll 4
    for (int jj = 0; jj < 16; jj++) {
        int lin = tid + jj * 256;
        int r = lin >> 5, c = (lin & 31) * 4;
        float4 v = make_float4(0.f, 0.f, 0.f, 0.f);
        if (row0 + r < Mtot) v = *(const float4*)&A[(row0 + r) * 128 + c];
        __nv_bfloat16 h0, l0, h1, l1, h2, l2, h3, l3;
        bf16split(v.x, h0, l0); bf16split(v.y, h1, l1);
        bf16split(v.z, h2, l2); bf16split(v.w, h3, l3);
        int o = r * 136 + c;
        sb[(G_AHI>>1) + o] = h0; sb[(G_AHI>>1) + o + 1] = h1; sb[(G_AHI>>1) + o + 2] = h2; sb[(G_AHI>>1) + o + 3] = h3;
        sb[(G_ALO>>1) + o] = l0; sb[(G_ALO>>1) + o + 1] = l1; sb[(G_ALO>>1) + o + 2] = l2; sb[(G_ALO>>1) + o + 3] = l3;
    }

    const int a_row = wm * 32 + (lane & 15);
    const int a_cs  = (lane >> 4) * 8;
    const int b_i   = lane >> 3;
    const int b_rp  = (b_i >> 1) * 8 + (lane & 7);
    const int b_cs  = (b_i & 1) * 8;
    const int er = lane >> 2;
    const int ec = (lane & 3) * 2;

#pragma unroll 1
    for (int nc = 0; nc < Ntiles; nc++) {
        const int col0 = nc * 128;

        float acc[2][8][4];
#pragma unroll
        for (int mt = 0; mt < 2; mt++)
#pragma unroll
            for (int nt = 0; nt < 8; nt++)
#pragma unroll
                for (int i = 0; i < 4; i++) acc[mt][nt][i] = 0.f;

#pragma unroll 1
        for (int kc = 0; kc < 2; kc++) {
            __syncthreads();
            // ---- stage W chunk [128 rows x 64 K] -> hi/lo, stride 72 ----
#pragma unroll
            for (int jj = 0; jj < 8; jj++) {
                int lin = tid + jj * 256;
                int r = lin >> 4, c = (lin & 15) * 4;
                float4 v = *(const float4*)&W[(size_t)(col0 + r) * 128 + kc * 64 + c];
                __nv_bfloat16 h0, l0, h1, l1, h2, l2, h3, l3;
                bf16split(v.x, h0, l0); bf16split(v.y, h1, l1);
                bf16split(v.z, h2, l2); bf16split(v.w, h3, l3);
                int o = r * 72 + c;
                sb[(G_WHI>>1) + o] = h0; sb[(G_WHI>>1) + o + 1] = h1; sb[(G_WHI>>1) + o + 2] = h2; sb[(G_WHI>>1) + o + 3] = h3;
                sb[(G_WLO>>1) + o] = l0; sb[(G_WLO>>1) + o + 1] = l1; sb[(G_WLO>>1) + o + 2] = l2; sb[(G_WLO>>1) + o + 3] = l3;
            }
            __syncthreads();

#pragma unroll
            for (int ks = 0; ks < 4; ks++) {
                uint32_t ah[2][4], al[2][4];
#pragma unroll
                for (int mt = 0; mt < 2; mt++) {
                    uint32_t off = (uint32_t)((a_row + mt * 16) * 136 + kc * 64 + ks * 16 + a_cs) * 2;
                    LDSM_X4(ah[mt][0], ah[mt][1], ah[mt][2], ah[mt][3], sbase + G_AHI + off);
                    LDSM_X4(al[mt][0], al[mt][1], al[mt][2], al[mt][3], sbase + G_ALO + off);
                }
                // process np in pairs; 3 waves of 8 independent mma each
#pragma unroll
                for (int npp = 0; npp < 2; npp++) {
                    uint32_t bh[2][4], bl[2][4];
#pragma unroll
                    for (int j = 0; j < 2; j++) {
                        int np = npp * 2 + j;
                        uint32_t off = (uint32_t)((wn * 64 + np * 16 + b_rp) * 72 + ks * 16 + b_cs) * 2;
                        LDSM_X4(bh[j][0], bh[j][1], bh[j][2], bh[j][3], sbase + G_WHI + off);
                        LDSM_X4(bl[j][0], bl[j][1], bl[j][2], bl[j][3], sbase + G_WLO + off);
                    }
                    // wave 1: hi*hi
#pragma unroll
                    for (int mt = 0; mt < 2; mt++)
#pragma unroll
                        for (int j = 0; j < 2; j++) {
                            int nt = (npp * 2 + j) * 2;
                            MMA_BF16(acc[mt][nt],     ah[mt], bh[j][0], bh[j][1]);
                            MMA_BF16(acc[mt][nt + 1], ah[mt], bh[j][2], bh[j][3]);
                        }
                    // wave 2: lo*hi
#pragma unroll
                    for (int mt = 0; mt < 2; mt++)
#pragma unroll
                        for (int j = 0; j < 2; j++) {
                            int nt = (npp * 2 + j) * 2;
                            MMA_BF16(acc[mt][nt],     al[mt], bh[j][0], bh[j][1]);
                            MMA_BF16(acc[mt][nt + 1], al[mt], bh[j][2], bh[j][3]);
                        }
                    // wave 3: hi*lo
#pragma unroll
                    for (int mt = 0; mt < 2; mt++)
#pragma unroll
                        for (int j = 0; j < 2; j++) {
                            int nt = (npp * 2 + j) * 2;
                            MMA_BF16(acc[mt][nt],     ah[mt], bl[j][0], bl[j][1]);
                            MMA_BF16(acc[mt][nt + 1], ah[mt], bl[j][2], bl[j][3]);
                        }
                }
            }
        }

        // ---- epilogue for this slab ----
#pragma unroll
        for (int mt = 0; mt < 2; mt++) {
            long r = row0 + wm * 32 + mt * 16 + er;
#pragma unroll
            for (int nt = 0; nt < 8; nt++) {
                int c = col0 + wn * 64 + nt * 8 + ec;
                float b0 = bias[c], b1 = bias[c + 1];
                if (r < Mtot)
                    *(float2*)&Out[r * Nout + c] =
                        make_float2(acc[mt][nt][0] + b0, acc[mt][nt][1] + b1);
                if (r + 8 < Mtot)
                    *(float2*)&Out[(r + 8) * Nout + c] =
                        make_float2(acc[mt][nt][2] + b0, acc[mt][nt][3] + b1);
            }
        }
    }
}

// ======================= comb = bias_table[rel_idx] + mask =======================
__global__ void comb_kernel(const float* __restrict__ mask,
                            const float* __restrict__ bias_table,
                            const int*   __restrict__ rel_idx)
{
    int idx = blockIdx.x * blockDim.x + threadIdx.x;
    const int total = NWIN * HEADS * N_TOK * N_TOK;
    if (idx >= total) return;
    int w   = idx / (HEADS * N_TOK * N_TOK);
    int rem = idx - w * (HEADS * N_TOK * N_TOK);
    int h   = rem / (N_TOK * N_TOK);
    int nm  = rem - h * (N_TOK * N_TOK);
    g_comb[idx] = bias_table[rel_idx[nm] * HEADS + h] + mask[w * (N_TOK * N_TOK) + nm];
}

// ======================= attention: register flash, wave-ordered QK^T =======================
#define TQH 0
#define TQL 30464
#define TKH 60928
#define TKL 91392
#define TVH 121856
#define TVL 152320
#define ATTN_SMEM 182784

__global__ __launch_bounds__(512, 1)
void attn_kernel()
{
    char* sb = smraw;
    const uint32_t sbase = smem_u32(sb);
    const int b    = blockIdx.x;
    const int tid  = threadIdx.x;
    const int lane = tid & 31;
    const int warp = tid >> 5;
    const int win  = b & (NWIN - 1);

    // zero V pad rows 98..111 (hi/lo)
    for (int i = tid; i < 14 * 68; i += 512) {
        int r = 98 + i / 68, c4 = (i % 68) * 2;
        *(uint32_t*)(sb + TVH + (r * 136 + c4) * 2) = 0u;
        *(uint32_t*)(sb + TVL + (r * 136 + c4) * 2) = 0u;
    }

    // ---- stage Q (scaled), K, V row-major bf16 hi/lo ----
    {
        const float* qk = g_qkv + (size_t)b * N_TOK * 384;
        for (int i = tid; i < N_TOK * 32; i += 512) {
            int m = i >> 5, c = (i & 31) * 4;
            const float* rp = qk + m * 384 + c;
            float4 q = *(const float4*)rp;
            float4 k = *(const float4*)(rp + 128);
            float4 v = *(const float4*)(rp + 256);
            q.x *= SCALE; q.y *= SCALE; q.z *= SCALE; q.w *= SCALE;
            __nv_bfloat16 hh[4], ll[4];
            bf16split(q.x, hh[0], ll[0]); bf16split(q.y, hh[1], ll[1]);
            bf16split(q.z, hh[2], ll[2]); bf16split(q.w, hh[3], ll[3]);
            *(uint2*)(sb + TQH + (m * 136 + c) * 2) = *(uint2*)hh;
            *(uint2*)(sb + TQL + (m * 136 + c) * 2) = *(uint2*)ll;
            bf16split(k.x, hh[0], ll[0]); bf16split(k.y, hh[1], ll[1]);
            bf16split(k.z, hh[2], ll[2]); bf16split(k.w, hh[3], ll[3]);
            *(uint2*)(sb + TKH + (m * 136 + c) * 2) = *(uint2*)hh;
            *(uint2*)(sb + TKL + (m * 136 + c) * 2) = *(uint2*)ll;
            bf16split(v.x, hh[0], ll[0]); bf16split(v.y, hh[1], ll[1]);
            bf16split(v.z, hh[2], ll[2]); bf16split(v.w, hh[3], ll[3]);
            *(uint2*)(sb + TVH + (m * 136 + c) * 2) = *(uint2*)hh;
            *(uint2*)(sb + TVL + (m * 136 + c) * 2) = *(uint2*)ll;
        }
    }
    __syncthreads();

    const int a_rp = lane & 15;
    const int a_cs = (lane >> 4) * 8;
    const int b_i  = lane >> 3;
    const int b_rp = (b_i >> 1) * 8 + (lane & 7);
    const int b_cs = (b_i & 1) * 8;
    const int t_rp = (b_i & 1) * 8 + (lane & 7);
    const int t_cs = (b_i >> 1) * 8;
    const int er   = lane >> 2;
    const int ec   = (lane & 3) * 2;

#pragma unroll 1
    for (int item = warp; item < 28; item += 16) {
        const int h  = item / 7;
        const int mt = item - h * 7;

        // ---- QK^T: wave-ordered over np pairs ----
        float acc[14][4];
#pragma unroll
        for (int nt = 0; nt < 14; nt++)
#pragma unroll
            for (int i = 0; i < 4; i++) acc[nt][i] = 0.f;

#pragma unroll
        for (int ks = 0; ks < 2; ks++) {
            const int kb = h * 32 + ks * 16;
            uint32_t ah[4], al[4];
            uint32_t aoff = (uint32_t)((mt * 16 + a_rp) * 136 + kb + a_cs) * 2;
            LDSM_X4(ah[0], ah[1], ah[2], ah[3], sbase + TQH + aoff);
            LDSM_X4(al[0], al[1], al[2], al[3], sbase + TQL + aoff);
#pragma unroll
            for (int npp = 0; npp < 3; npp++) {
                uint32_t kh[2][4], kl[2][4];
#pragma unroll
                for (int j = 0; j < 2; j++) {
                    int np = npp * 2 + j;
                    uint32_t boff = (uint32_t)((np * 16 + b_rp) * 136 + kb + b_cs) * 2;
                    LDSM_X4(kh[j][0], kh[j][1], kh[j][2], kh[j][3], sbase + TKH + boff);
                    LDSM_X4(kl[j][0], kl[j][1], kl[j][2], kl[j][3], sbase + TKL + boff);
                }
                // wave 1: hi*hi (4 independent accs)
#pragma unroll
                for (int j = 0; j < 2; j++) {
                    int nt = (npp * 2 + j) * 2;
                    MMA_BF16(acc[nt],     ah, kh[j][0], kh[j][1]);
                    MMA_BF16(acc[nt + 1], ah, kh[j][2], kh[j][3]);
                }
                // wave 2: lo*hi
#pragma unroll
                for (int j = 0; j < 2; j++) {
                    int nt = (npp * 2 + j) * 2;
                    MMA_BF16(acc[nt],     al, kh[j][0], kh[j][1]);
                    MMA_BF16(acc[nt + 1], al, kh[j][2], kh[j][3]);
                }
                // wave 3: hi*lo
#pragma unroll
                for (int j = 0; j < 2; j++) {
                    int nt = (npp * 2 + j) * 2;
                    MMA_BF16(acc[nt],     ah, kl[j][0], kl[j][1]);
                    MMA_BF16(acc[nt + 1], ah, kl[j][2], kl[j][3]);
                }
            }
            // np = 6 (last single)
            {
                uint32_t boff = (uint32_t)((6 * 16 + b_rp) * 136 + kb + b_cs) * 2;
                uint32_t h0, h1, h2, h3, l0, l1, l2, l3;
                LDSM_X4(h0, h1, h2, h3, sbase + TKH + boff);
                LDSM_X4(l0, l1, l2, l3, sbase + TKL + boff);
                MMA_BF16(acc[12], ah, h0, h1);
                MMA_BF16(acc[13], ah, h2, h3);
                MMA_BF16(acc[12], al, h0, h1);
                MMA_BF16(acc[13], al, h2, h3);
                MMA_BF16(acc[12], ah, l0, l1);
                MMA_BF16(acc[13], ah, l2, l3);
            }
        }

        // ---- softmax in registers ----
        const float* combh = g_comb + (size_t)(win * HEADS + h) * N_TOK * N_TOK;
#pragma unroll
        for (int rr = 0; rr < 2; rr++) {
            int n = mt * 16 + er + rr * 8;
            bool rowok = (n < N_TOK);
            int  nc = rowok ? n : 0;
            float mx = -1e30f;
#pragma unroll
            for (int nt = 0; nt < 14; nt++) {
                int m = nt * 8 + ec;
                float v0 = -1e30f, v1 = -1e30f;
                if (m < N_TOK) {
                    float2 cb = *(const float2*)&combh[nc * N_TOK + m];
                    v0 = acc[nt][rr * 2]     + cb.x;
                    v1 = acc[nt][rr * 2 + 1] + cb.y;
                }
                acc[nt][rr * 2] = v0; acc[nt][rr * 2 + 1] = v1;
                mx = fmaxf(mx, fmaxf(v0, v1));
            }
            mx = fmaxf(mx, __shfl_xor_sync(0xffffffffu, mx, 1));
            mx = fmaxf(mx, __shfl_xor_sync(0xffffffffu, mx, 2));
            float sum = 0.f;
#pragma unroll
            for (int nt = 0; nt < 14; nt++) {
                float e0 = __expf(acc[nt][rr * 2]     - mx);
                float e1 = __expf(acc[nt][rr * 2 + 1] - mx);
                acc[nt][rr * 2] = e0; acc[nt][rr * 2 + 1] = e1;
                sum += e0 + e1;
            }
            sum += __shfl_xor_sync(0xffffffffu, sum, 1);
            sum += __shfl_xor_sync(0xffffffffu, sum, 2);
            float inv = rowok ? __fdividef(1.f, sum) : 0.f;
#pragma unroll
            for (int nt = 0; nt < 14; nt++) {
                acc[nt][rr * 2] *= inv; acc[nt][rr * 2 + 1] *= inv;
            }
        }

        // ---- PV: P in registers, V via ldmatrix.trans ----
        float oacc[4][4];
#pragma unroll
        for (int nt = 0; nt < 4; nt++)
#pragma unroll
            for (int i = 0; i < 4; i++) oacc[nt][i] = 0.f;

#pragma unroll
        for (int t = 0; t < 7; t++) {
            uint32_t ph[4], pl[4];
            ph[0] = pack_split(acc[2*t][0],   acc[2*t][1],   pl[0]);
            ph[1] = pack_split(acc[2*t][2],   acc[2*t][3],   pl[1]);
            ph[2] = pack_split(acc[2*t+1][0], acc[2*t+1][1], pl[2]);
            ph[3] = pack_split(acc[2*t+1][2], acc[2*t+1][3], pl[3]);
            uint32_t b0h[4], b1h[4], b0l[4], b1l[4];
            {
                uint32_t boff0 = (uint32_t)((t * 16 + t_rp) * 136 + h * 32 + t_cs) * 2;
                uint32_t boff1 = (uint32_t)((t * 16 + t_rp) * 136 + h * 32 + 16 + t_cs) * 2;
                LDSM_X4_T(b0h[0], b0h[1], b0h[2], b0h[3], sbase + TVH + boff0);
                LDSM_X4_T(b0l[0], b0l[1], b0l[2], b0l[3], sbase + TVL + boff0);
                LDSM_X4_T(b1h[0], b1h[1], b1h[2], b1h[3], sbase + TVH + boff1);
                LDSM_X4_T(b1l[0], b1l[1], b1l[2], b1l[3], sbase + TVL + boff1);
            }
            // wave 1: hi P * hi V (4 independent)
            MMA_BF16(oacc[0], ph, b0h[0], b0h[1]);
            MMA_BF16(oacc[1], ph, b0h[2], b0h[3]);
            MMA_BF16(oacc[2], ph, b1h[0], b1h[1]);
            MMA_BF16(oacc[3], ph, b1h[2], b1h[3]);
            // wave 2: lo P * hi V
            MMA_BF16(oacc[0], pl, b0h[0], b0h[1]);
            MMA_BF16(oacc[1], pl, b0h[2], b0h[3]);
            MMA_BF16(oacc[2], pl, b1h[0], b1h[1]);
            MMA_BF16(oacc[3], pl, b1h[2], b1h[3]);
            // wave 3: hi P * lo V
            MMA_BF16(oacc[0], ph, b0l[0], b0l[1]);
            MMA_BF16(oacc[1], ph, b0l[2], b0l[3]);
            MMA_BF16(oacc[2], ph, b1l[0], b1l[1]);
            MMA_BF16(oacc[3], ph, b1l[2], b1l[3]);
        }

        // ---- store O ----
        const int n0 = mt * 16 + er;
#pragma unroll
        for (int nt = 0; nt < 4; nt++) {
            int ch = h * 32 + nt * 8 + ec;
            if (n0 < N_TOK)
                *(float2*)&g_o[((size_t)b * N_TOK + n0) * 128 + ch] =
                    make_float2(oacc[nt][0], oacc[nt][1]);
            if (n0 + 8 < N_TOK)
                *(float2*)&g_o[((size_t)b * N_TOK + n0 + 8) * 128 + ch] =
                    make_float2(oacc[nt][2], oacc[nt][3]);
        }
    }
}

// ======================= launch =======================
extern "C" void kernel_launch(void* const* d_in, const int* in_sizes, int n_in,
                              void* d_out, int out_size)
{
    const float* x          = (const float*)d_in[0];
    const float* mask       = (const float*)d_in[1];
    const float* qkv_w      = (const float*)d_in[2];
    const float* qkv_b      = (const float*)d_in[3];
    const float* proj_w     = (const float*)d_in[4];
    const float* proj_b     = (const float*)d_in[5];
    const float* bias_table = (const float*)d_in[6];
    const int*   rel_idx    = (const int*)d_in[7];
    float*       out        = (float*)d_out;

    const int B    = in_sizes[0] / (N_TOK * DIM);
    const int Mtot = B * N_TOK;
    const int mtiles = (Mtot + 127) / 128;

    float *qkv_ptr, *o_ptr;
    cudaGetSymbolAddress((void**)&qkv_ptr, g_qkv);
    cudaGetSymbolAddress((void**)&o_ptr, g_o);

    cudaFuncSetAttribute(gemm_bf16x3,
                         cudaFuncAttributeMaxDynamicSharedMemorySize, G_SMEM_BYTES);
    cudaFuncSetAttribute(attn_kernel,
                         cudaFuncAttributeMaxDynamicSharedMemorySize, ATTN_SMEM);

    {
        const int total = NWIN * HEADS * N_TOK * N_TOK;
        comb_kernel<<<(total + 255) / 256, 256>>>(mask, bias_table, rel_idx);
    }
    gemm_bf16x3<<<mtiles, 256, G_SMEM_BYTES>>>(x, qkv_w, qkv_b, qkv_ptr, 384, Mtot, 3);
    attn_kernel<<<B, 512, ATTN_SMEM>>>();
    gemm_bf16x3<<<mtiles, 256, G_SMEM_BYTES>>>(o_ptr, proj_w, proj_b, out, 128, Mtot, 1);
}

// round 17
// speedup vs baseline: 1.0711x; 1.0481x over previous
#include <cuda_runtime.h>
#include <cuda_bf16.h>
#include <cstdint>

#define N_TOK 98
#define DIM   128
#define HEADS 4
#define NWIN  64
#define SCALE 0.17677669529663687f

#define MAX_B    2048
#define MAX_MTOT (MAX_B * N_TOK)

__device__ float g_qkv[(size_t)MAX_MTOT * 384];
__device__ float g_o[(size_t)MAX_MTOT * 128];
__device__ float g_comb[NWIN * HEADS * N_TOK * N_TOK];

// ======================= helpers =======================
static __device__ __forceinline__ uint32_t smem_u32(const void* p) {
    uint32_t a;
    asm("{ .reg .u64 t; cvta.to.shared.u64 t, %1; cvt.u32.u64 %0, t; }" : "=r"(a) : "l"(p));
    return a;
}
#define LDSM_X4(r0, r1, r2, r3, addr)                                          \
    asm volatile("ldmatrix.sync.aligned.m8n8.x4.shared.b16 {%0,%1,%2,%3}, [%4];" \
                 : "=r"(r0), "=r"(r1), "=r"(r2), "=r"(r3) : "r"(addr))
#define LDSM_X4_T(r0, r1, r2, r3, addr)                                        \
    asm volatile("ldmatrix.sync.aligned.m8n8.x4.trans.shared.b16 {%0,%1,%2,%3}, [%4];" \
                 : "=r"(r0), "=r"(r1), "=r"(r2), "=r"(r3) : "r"(addr))
#define MMA_BF16(c, a, b0, b1)                                                 \
    asm volatile("mma.sync.aligned.m16n8k16.row.col.f32.bf16.bf16.f32 "        \
                 "{%0,%1,%2,%3}, {%4,%5,%6,%7}, {%8,%9}, {%0,%1,%2,%3};"       \
                 : "+f"((c)[0]), "+f"((c)[1]), "+f"((c)[2]), "+f"((c)[3])      \
                 : "r"((a)[0]), "r"((a)[1]), "r"((a)[2]), "r"((a)[3]),         \
                   "r"(b0), "r"(b1))

static __device__ __forceinline__ void bf16split(float a, __nv_bfloat16& h, __nv_bfloat16& l) {
    h = __float2bfloat16_rn(a);
    l = __float2bfloat16_rn(a - __bfloat162float(h));
}
static __device__ __forceinline__ uint32_t pack_split(float a, float b, uint32_t& lo) {
    __nv_bfloat16 ah, al, bh, bl;
    bf16split(a, ah, al); bf16split(b, bh, bl);
    uint16_t ahu = *(uint16_t*)&ah, alu = *(uint16_t*)&al;
    uint16_t bhu = *(uint16_t*)&bh, blu = *(uint16_t*)&bl;
    lo = ((uint32_t)blu << 16) | alu;
    return ((uint32_t)bhu << 16) | ahu;
}
// swizzled byte offset for [row][128ch] bf16 arrays (row stride 256B)
static __device__ __forceinline__ uint32_t swz(int r, int cb) {
    return (uint32_t)(((r << 8) + cb) ^ ((r & 7) << 4));
}

extern __shared__ char smraw[];

// ======================= bf16x3 GEMM (R11 verbatim) ====================
#define G_AHI 0
#define G_ALO 34816
#define G_WHI 69632
#define G_WLO 88064
#define G_SMEM_BYTES 106496

__global__ __launch_bounds__(256, 2)
void gemm_bf16x3(const float* __restrict__ A,
                 const float* __restrict__ W,
                 const float* __restrict__ bias,
                 float* __restrict__ Out,
                 int Nout, int Mtot, int Ntiles)
{
    __nv_bfloat16* sb = (__nv_bfloat16*)smraw;
    const uint32_t sbase = smem_u32(sb);
    const int tid  = threadIdx.x;
    const int lane = tid & 31;
    const int warp = tid >> 5;
    const int wm   = warp & 3;
    const int wn   = warp >> 2;
    const long row0 = (long)blockIdx.x * 128;

#pragma unroll 4
    for (int jj = 0; jj < 16; jj++) {
        int lin = tid + jj * 256;
        int r = lin >> 5, c = (lin & 31) * 4;
        float4 v = make_float4(0.f, 0.f, 0.f, 0.f);
        if (row0 + r < Mtot) v = *(const float4*)&A[(row0 + r) * 128 + c];
        __nv_bfloat16 h0, l0, h1, l1, h2, l2, h3, l3;
        bf16split(v.x, h0, l0); bf16split(v.y, h1, l1);
        bf16split(v.z, h2, l2); bf16split(v.w, h3, l3);
        int o = r * 136 + c;
        sb[(G_AHI>>1) + o] = h0; sb[(G_AHI>>1) + o + 1] = h1; sb[(G_AHI>>1) + o + 2] = h2; sb[(G_AHI>>1) + o + 3] = h3;
        sb[(G_ALO>>1) + o] = l0; sb[(G_ALO>>1) + o + 1] = l1; sb[(G_ALO>>1) + o + 2] = l2; sb[(G_ALO>>1) + o + 3] = l3;
    }

    const int a_row = wm * 32 + (lane & 15);
    const int a_cs  = (lane >> 4) * 8;
    const int b_i   = lane >> 3;
    const int b_rp  = (b_i >> 1) * 8 + (lane & 7);
    const int b_cs  = (b_i & 1) * 8;
    const int er = lane >> 2;
    const int ec = (lane & 3) * 2;

#pragma unroll 1
    for (int nc = 0; nc < Ntiles; nc++) {
        const int col0 = nc * 128;
        float acc[2][8][4];
#pragma unroll
        for (int mt = 0; mt < 2; mt++)
#pragma unroll
            for (int nt = 0; nt < 8; nt++)
#pragma unroll
                for (int i = 0; i < 4; i++) acc[mt][nt][i] = 0.f;

#pragma unroll 1
        for (int kc = 0; kc < 2; kc++) {
            __syncthreads();
#pragma unroll
            for (int jj = 0; jj < 8; jj++) {
                int lin = tid + jj * 256;
                int r = lin >> 4, c = (lin & 15) * 4;
                float4 v = *(const float4*)&W[(size_t)(col0 + r) * 128 + kc * 64 + c];
                __nv_bfloat16 h0, l0, h1, l1, h2, l2, h3, l3;
                bf16split(v.x, h0, l0); bf16split(v.y, h1, l1);
                bf16split(v.z, h2, l2); bf16split(v.w, h3, l3);
                int o = r * 72 + c;
                sb[(G_WHI>>1) + o] = h0; sb[(G_WHI>>1) + o + 1] = h1; sb[(G_WHI>>1) + o + 2] = h2; sb[(G_WHI>>1) + o + 3] = h3;
                sb[(G_WLO>>1) + o] = l0; sb[(G_WLO>>1) + o + 1] = l1; sb[(G_WLO>>1) + o + 2] = l2; sb[(G_WLO>>1) + o + 3] = l3;
            }
            __syncthreads();

#pragma unroll
            for (int ks = 0; ks < 4; ks++) {
                uint32_t ah[2][4], al[2][4];
#pragma unroll
                for (int mt = 0; mt < 2; mt++) {
                    uint32_t off = (uint32_t)((a_row + mt * 16) * 136 + kc * 64 + ks * 16 + a_cs) * 2;
                    LDSM_X4(ah[mt][0], ah[mt][1], ah[mt][2], ah[mt][3], sbase + G_AHI + off);
                    LDSM_X4(al[mt][0], al[mt][1], al[mt][2], al[mt][3], sbase + G_ALO + off);
                }
#pragma unroll
                for (int np = 0; np < 4; np++) {
                    uint32_t off = (uint32_t)((wn * 64 + np * 16 + b_rp) * 72 + ks * 16 + b_cs) * 2;
                    uint32_t h0, h1, h2, h3, l0, l1, l2, l3;
                    LDSM_X4(h0, h1, h2, h3, sbase + G_WHI + off);
                    LDSM_X4(l0, l1, l2, l3, sbase + G_WLO + off);
#pragma unroll
                    for (int mt = 0; mt < 2; mt++) {
                        MMA_BF16(acc[mt][np * 2],     ah[mt], h0, h1);
                        MMA_BF16(acc[mt][np * 2],     al[mt], h0, h1);
                        MMA_BF16(acc[mt][np * 2],     ah[mt], l0, l1);
                        MMA_BF16(acc[mt][np * 2 + 1], ah[mt], h2, h3);
                        MMA_BF16(acc[mt][np * 2 + 1], al[mt], h2, h3);
                        MMA_BF16(acc[mt][np * 2 + 1], ah[mt], l2, l3);
                    }
                }
            }
        }

#pragma unroll
        for (int mt = 0; mt < 2; mt++) {
            long r = row0 + wm * 32 + mt * 16 + er;
#pragma unroll
            for (int nt = 0; nt < 8; nt++) {
                int c = col0 + wn * 64 + nt * 8 + ec;
                float b0 = bias[c], b1 = bias[c + 1];
                if (r < Mtot)
                    *(float2*)&Out[r * Nout + c] =
                        make_float2(acc[mt][nt][0] + b0, acc[mt][nt][1] + b1);
                if (r + 8 < Mtot)
                    *(float2*)&Out[(r + 8) * Nout + c] =
                        make_float2(acc[mt][nt][2] + b0, acc[mt][nt][3] + b1);
            }
        }
    }
}

// ======================= comb = bias_table[rel_idx] + mask =======================
__global__ void comb_kernel(const float* __restrict__ mask,
                            const float* __restrict__ bias_table,
                            const int*   __restrict__ rel_idx)
{
    int idx = blockIdx.x * blockDim.x + threadIdx.x;
    const int total = NWIN * HEADS * N_TOK * N_TOK;
    if (idx >= total) return;
    int w   = idx / (HEADS * N_TOK * N_TOK);
    int rem = idx - w * (HEADS * N_TOK * N_TOK);
    int h   = rem / (N_TOK * N_TOK);
    int nm  = rem - h * (N_TOK * N_TOK);
    g_comb[idx] = bias_table[rel_idx[nm] * HEADS + h] + mask[w * (N_TOK * N_TOK) + nm];
}

// ======================= attention v6: 2 CTAs/SM, Q from gmem, swizzled K/V ============
#define AKH 0
#define AKL 28672
#define AVH 57344
#define AVL 86016
#define ATTN_SMEM 114688

__global__ __launch_bounds__(256, 2)
void attn_kernel()
{
    char* sb = smraw;
    const uint32_t sbase = smem_u32(sb);
    const int b    = blockIdx.x;
    const int tid  = threadIdx.x;
    const int lane = tid & 31;
    const int warp = tid >> 5;
    const int win  = b & (NWIN - 1);

    const float* qk = g_qkv + (size_t)b * N_TOK * 384;

    // zero V pad rows 98..111 (hi/lo), swizzled
    for (int i = tid; i < 14 * 32; i += 256) {
        int r = 98 + (i >> 5), u = i & 31;        // u: uint2 index (4 ch)
        uint32_t o = swz(r, u * 8);
        *(uint2*)(sb + AVH + o) = make_uint2(0u, 0u);
        *(uint2*)(sb + AVL + o) = make_uint2(0u, 0u);
    }

    // ---- stage K, V (swizzled, bf16 hi/lo) ----
    for (int i = tid; i < N_TOK * 32; i += 256) {
        int m = i >> 5, c = (i & 31) * 4;
        const float* rp = qk + m * 384 + c;
        float4 k = *(const float4*)(rp + 128);
        float4 v = *(const float4*)(rp + 256);
        __nv_bfloat16 hh[4], ll[4];
        uint32_t o = swz(m, c * 2);
        bf16split(k.x, hh[0], ll[0]); bf16split(k.y, hh[1], ll[1]);
        bf16split(k.z, hh[2], ll[2]); bf16split(k.w, hh[3], ll[3]);
        *(uint2*)(sb + AKH + o) = *(uint2*)hh;
        *(uint2*)(sb + AKL + o) = *(uint2*)ll;
        bf16split(v.x, hh[0], ll[0]); bf16split(v.y, hh[1], ll[1]);
        bf16split(v.z, hh[2], ll[2]); bf16split(v.w, hh[3], ll[3]);
        *(uint2*)(sb + AVH + o) = *(uint2*)hh;
        *(uint2*)(sb + AVL + o) = *(uint2*)ll;
    }
    __syncthreads();

    const int b_i  = lane >> 3;
    const int b_rp = (b_i >> 1) * 8 + (lane & 7);
    const int b_cs = (b_i & 1) * 8;
    const int t_rp = (b_i & 1) * 8 + (lane & 7);
    const int t_cs = (b_i >> 1) * 8;
    const int er   = lane >> 2;
    const int ec   = (lane & 3) * 2;
    const int g    = lane >> 2;
    const int tig  = lane & 3;

#pragma unroll 1
    for (int item = warp; item < 28; item += 8) {
        const int h  = item / 7;
        const int mt = item - h * 7;

        // ---- QK^T (Q fragments straight from gmem, split in regs) ----
        float acc[14][4];
#pragma unroll
        for (int nt = 0; nt < 14; nt++)
#pragma unroll
            for (int i = 0; i < 4; i++) acc[nt][i] = 0.f;

        const int r0 = mt * 16 + g;
        const int r1 = r0 + 8;
        const int r0c = (r0 < N_TOK) ? r0 : N_TOK - 1;
        const int r1c = (r1 < N_TOK) ? r1 : N_TOK - 1;

#pragma unroll
        for (int ks = 0; ks < 2; ks++) {
            const int kb = h * 32 + ks * 16;
            const float* q0 = qk + r0c * 384 + kb + tig * 2;
            const float* q1 = qk + r1c * 384 + kb + tig * 2;
            float2 q00 = *(const float2*)q0;
            float2 q01 = *(const float2*)(q0 + 8);
            float2 q10 = *(const float2*)q1;
            float2 q11 = *(const float2*)(q1 + 8);
            uint32_t ah[4], al[4];
            ah[0] = pack_split(q00.x * SCALE, q00.y * SCALE, al[0]);
            ah[1] = pack_split(q10.x * SCALE, q10.y * SCALE, al[1]);
            ah[2] = pack_split(q01.x * SCALE, q01.y * SCALE, al[2]);
            ah[3] = pack_split(q11.x * SCALE, q11.y * SCALE, al[3]);
#pragma unroll
            for (int np = 0; np < 7; np++) {
                uint32_t boff = swz(np * 16 + b_rp, (kb + b_cs) * 2);
                uint32_t h0, h1, h2, h3, l0, l1, l2, l3;
                LDSM_X4(h0, h1, h2, h3, sbase + AKH + boff);
                LDSM_X4(l0, l1, l2, l3, sbase + AKL + boff);
                MMA_BF16(acc[np * 2],     ah, h0, h1);
                MMA_BF16(acc[np * 2],     al, h0, h1);
                MMA_BF16(acc[np * 2],     ah, l0, l1);
                MMA_BF16(acc[np * 2 + 1], ah, h2, h3);
                MMA_BF16(acc[np * 2 + 1], al, h2, h3);
                MMA_BF16(acc[np * 2 + 1], ah, l2, l3);
            }
        }

        // ---- softmax in registers ----
        const float* combh = g_comb + (size_t)(win * HEADS + h) * N_TOK * N_TOK;
#pragma unroll
        for (int rr = 0; rr < 2; rr++) {
            int n = mt * 16 + er + rr * 8;
            bool rowok = (n < N_TOK);
            int  nc = rowok ? n : 0;
            float mx = -1e30f;
#pragma unroll
            for (int nt = 0; nt < 14; nt++) {
                int m = nt * 8 + ec;
                float v0 = -1e30f, v1 = -1e30f;
                if (m < N_TOK) {
                    float2 cb = *(const float2*)&combh[nc * N_TOK + m];
                    v0 = acc[nt][rr * 2]     + cb.x;
                    v1 = acc[nt][rr * 2 + 1] + cb.y;
                }
                acc[nt][rr * 2] = v0; acc[nt][rr * 2 + 1] = v1;
                mx = fmaxf(mx, fmaxf(v0, v1));
            }
            mx = fmaxf(mx, __shfl_xor_sync(0xffffffffu, mx, 1));
            mx = fmaxf(mx, __shfl_xor_sync(0xffffffffu, mx, 2));
            float sum = 0.f;
#pragma unroll
            for (int nt = 0; nt < 14; nt++) {
                float e0 = __expf(acc[nt][rr * 2]     - mx);
                float e1 = __expf(acc[nt][rr * 2 + 1] - mx);
                acc[nt][rr * 2] = e0; acc[nt][rr * 2 + 1] = e1;
                sum += e0 + e1;
            }
            sum += __shfl_xor_sync(0xffffffffu, sum, 1);
            sum += __shfl_xor_sync(0xffffffffu, sum, 2);
            float inv = rowok ? __fdividef(1.f, sum) : 0.f;
#pragma unroll
            for (int nt = 0; nt < 14; nt++) {
                acc[nt][rr * 2] *= inv; acc[nt][rr * 2 + 1] *= inv;
            }
        }

        // ---- PV: P in registers, V via ldmatrix.trans (swizzled) ----
        float oacc[4][4];
#pragma unroll
        for (int nt = 0; nt < 4; nt++)
#pragma unroll
            for (int i = 0; i < 4; i++) oacc[nt][i] = 0.f;

#pragma unroll
        for (int t = 0; t < 7; t++) {
            uint32_t ph[4], pl[4];
            ph[0] = pack_split(acc[2*t][0],   acc[2*t][1],   pl[0]);
            ph[1] = pack_split(acc[2*t][2],   acc[2*t][3],   pl[1]);
            ph[2] = pack_split(acc[2*t+1][0], acc[2*t+1][1], pl[2]);
            ph[3] = pack_split(acc[2*t+1][2], acc[2*t+1][3], pl[3]);
#pragma unroll
            for (int np = 0; np < 2; np++) {
                uint32_t boff = swz(t * 16 + t_rp, (h * 32 + np * 16 + t_cs) * 2);
                uint32_t h0, h1, h2, h3, l0, l1, l2, l3;
                LDSM_X4_T(h0, h1, h2, h3, sbase + AVH + boff);
                LDSM_X4_T(l0, l1, l2, l3, sbase + AVL + boff);
                MMA_BF16(oacc[np * 2],     ph, h0, h1);
                MMA_BF16(oacc[np * 2],     pl, h0, h1);
                MMA_BF16(oacc[np * 2],     ph, l0, l1);
                MMA_BF16(oacc[np * 2 + 1], ph, h2, h3);
                MMA_BF16(oacc[np * 2 + 1], pl, h2, h3);
                MMA_BF16(oacc[np * 2 + 1], ph, l2, l3);
            }
        }

        // ---- store O ----
        const int n0 = mt * 16 + er;
#pragma unroll
        for (int nt = 0; nt < 4; nt++) {
            int ch = h * 32 + nt * 8 + ec;
            if (n0 < N_TOK)
                *(float2*)&g_o[((size_t)b * N_TOK + n0) * 128 + ch] =
                    make_float2(oacc[nt][0], oacc[nt][1]);
            if (n0 + 8 < N_TOK)
                *(float2*)&g_o[((size_t)b * N_TOK + n0 + 8) * 128 + ch] =
                    make_float2(oacc[nt][2], oacc[nt][3]);
        }
    }
}

// ======================= launch =======================
extern "C" void kernel_launch(void* const* d_in, const int* in_sizes, int n_in,
                              void* d_out, int out_size)
{
    const float* x          = (const float*)d_in[0];
    const float* mask       = (const float*)d_in[1];
    const float* qkv_w      = (const float*)d_in[2];
    const float* qkv_b      = (const float*)d_in[3];
    const float* proj_w     = (const float*)d_in[4];
    const float* proj_b     = (const float*)d_in[5];
    const float* bias_table = (const float*)d_in[6];
    const int*   rel_idx    = (const int*)d_in[7];
    float*       out        = (float*)d_out;

    const int B    = in_sizes[0] / (N_TOK * DIM);
    const int Mtot = B * N_TOK;
    const int mtiles = (Mtot + 127) / 128;

    float *qkv_ptr, *o_ptr;
    cudaGetSymbolAddress((void**)&qkv_ptr, g_qkv);
    cudaGetSymbolAddress((void**)&o_ptr, g_o);

    cudaFuncSetAttribute(gemm_bf16x3,
                         cudaFuncAttributeMaxDynamicSharedMemorySize, G_SMEM_BYTES);
    cudaFuncSetAttribute(attn_kernel,
                         cudaFuncAttributeMaxDynamicSharedMemorySize, ATTN_SMEM);

    {
        const int total = NWIN * HEADS * N_TOK * N_TOK;
        comb_kernel<<<(total + 255) / 256, 256>>>(mask, bias_table, rel_idx);
    }
    gemm_bf16x3<<<mtiles, 256, G_SMEM_BYTES>>>(x, qkv_w, qkv_b, qkv_ptr, 384, Mtot, 3);
    attn_kernel<<<B, 256, ATTN_SMEM>>>();
    gemm_bf16x3<<<mtiles, 256, G_SMEM_BYTES>>>(o_ptr, proj_w, proj_b, out, 128, Mtot, 1);
}